// round 1
// baseline (speedup 1.0000x reference)
#include <cuda_runtime.h>
#include <math.h>

// ---------------------------------------------------------------------------
// PET MLEM step: TOR forward projection + listmode backprojection, 3 LOR sets.
// GRID = 128^3, CENTER = 0, SIZE = 214, N_LORS = 65536 per direction.
// ---------------------------------------------------------------------------

#define NG   128
#define NG2  (128 * 128)
#define NG3  (128 * 128 * 128)

__device__ float g_imgT[NG3];  // imgT[a][b][c] = image[a][c][b]
__device__ float g_bp  [NG3];  // backprojection accumulator, native (z,y dirs)
__device__ float g_bpT [NG3];  // bpT[a][b][c] corresponds to image voxel (a,c,b)  (x dir)

__constant__ float C_VOX    = 1.671875f;          // 214/128, exact in fp32
__constant__ float C_XMIN   = -107.0f;
// sigma^2 = vox^2/pi ; 1/(2 sigma^2) = pi/(2 vox^2)
__constant__ float C_INV2S2 = 0.561975285171464f; // pi / (2 * 1.671875^2)

// ---------------------------------------------------------------------------
// prep: build transposed image, zero both accumulators
// ---------------------------------------------------------------------------
__global__ void prep_kernel(const float* __restrict__ image) {
    int tid = blockIdx.x * blockDim.x + threadIdx.x;
    if (tid >= NG3) return;
    int a = tid >> 14;
    int b = (tid >> 7) & 127;
    int c = tid & 127;
    // imgT[a][c][b] = image[a][b][c]
    g_imgT[(a << 14) + (c << 7) + b] = image[tid];
    g_bp [tid] = 0.0f;
    g_bpT[tid] = 0.0f;
}

// ---------------------------------------------------------------------------
// LOR kernel: one warp per LOR. Lane L handles planes {L, L+32, L+64, L+96}.
//   address of voxel (i, j, plane k) = i*SI + j*SJ + k
//   z-dir: SI=16384, SJ=128   (img = image,  bp = g_bp)
//   y-dir: SI=128,   SJ=16384 (img = image,  bp = g_bp)
//   x-dir: SI=128,   SJ=16384 (img = g_imgT, bp = g_bpT)
// ---------------------------------------------------------------------------
template <int SI, int SJ>
__global__ __launch_bounds__(256)
void lor_kernel(const float* __restrict__ lors,   // [6, n] row-major
                const float* __restrict__ img,
                float* __restrict__ bp,
                int n) {
    const int warp = blockIdx.x * 8 + (threadIdx.x >> 5);
    if (warp >= n) return;
    const int lane = threadIdx.x & 31;

    const float p1x = lors[0 * n + warp];
    const float p1y = lors[1 * n + warp];
    const float p1z = lors[2 * n + warp];
    const float p2x = lors[3 * n + warp];
    const float p2y = lors[4 * n + warp];
    const float p2z = lors[5 * n + warp];

    const float dx  = p2x - p1x;
    const float dy  = p2y - p1y;
    const float dzr = p2z - p1z;
    const float L   = sqrtf(dx * dx + dy * dy + dzr * dzr);
    const float dz  = (fabsf(dzr) < 1e-6f) ? 1e-6f : dzr;
    const float dl  = C_VOX * L / fabsf(dz);

    float ex[4][3];
    float ey[4][3];
    int   ib[4];
    int   jb[4];

    float acc = 0.0f;

#pragma unroll
    for (int q = 0; q < 4; q++) {
        const int   k  = lane + 32 * q;
        const float zc = C_XMIN + ((float)k + 0.5f) * C_VOX;     // exact
        const float t  = (zc - p1z) / dz;                        // IEEE div
        const bool  tok = (t >= 0.0f) && (t <= 1.0f);
        // unfused mul+add to match the reference's separate ops
        const float xs = __fadd_rn(p1x, __fmul_rn(t, dx));
        const float ys = __fadd_rn(p1y, __fmul_rn(t, dy));
        const float fi = __fadd_rn(__fdiv_rn(__fsub_rn(xs, C_XMIN), C_VOX), -0.5f);
        const float fj = __fadd_rn(__fdiv_rn(__fsub_rn(ys, C_XMIN), C_VOX), -0.5f);
        const int i0 = __float2int_rn(fi);   // round half-to-even, like jnp.round
        const int j0 = __float2int_rn(fj);
        ib[q] = i0;
        jb[q] = j0;
        const float axc = (float)i0 - fi;    // offset in voxel units
        const float ayc = (float)j0 - fj;

#pragma unroll
        for (int o = 0; o < 3; o++) {
            const float du = (axc + (float)(o - 1)) * C_VOX;
            const float eu = __expf(-du * du * C_INV2S2);
            const int   ii = i0 + o - 1;
            ex[q][o] = (tok && ii >= 0 && ii < NG) ? eu : 0.0f;

            const float dv = (ayc + (float)(o - 1)) * C_VOX;
            const float ev = __expf(-dv * dv * C_INV2S2);
            const int   jj = j0 + o - 1;
            ey[q][o] = (jj >= 0 && jj < NG) ? ev : 0.0f;
        }

        // forward gather (coalesced along k across the warp)
        if (tok) {
#pragma unroll
            for (int oi = 0; oi < 3; oi++) {
                const int ii = min(max(i0 + oi - 1, 0), NG - 1);
                float inner = 0.0f;
#pragma unroll
                for (int oj = 0; oj < 3; oj++) {
                    const int jj = min(max(j0 + oj - 1, 0), NG - 1);
                    inner = fmaf(ey[q][oj], __ldg(&img[ii * SI + jj * SJ + k]), inner);
                }
                acc = fmaf(ex[q][oi], inner, acc);
            }
        }
    }

    // warp-reduce line integral
#pragma unroll
    for (int s = 16; s > 0; s >>= 1)
        acc += __shfl_xor_sync(0xffffffffu, acc, s);

    const float proj = acc * dl;
    const float scl  = dl / (proj + 1e-8f);

    // backprojection scatter (atomics, coalesced along k across the warp)
#pragma unroll
    for (int q = 0; q < 4; q++) {
        const int k = lane + 32 * q;
#pragma unroll
        for (int oi = 0; oi < 3; oi++) {
            const float exi = ex[q][oi];
            const int   ii  = min(max(ib[q] + oi - 1, 0), NG - 1);
#pragma unroll
            for (int oj = 0; oj < 3; oj++) {
                const float w = exi * ey[q][oj];
                if (w != 0.0f) {
                    const int jj = min(max(jb[q] + oj - 1, 0), NG - 1);
                    atomicAdd(&bp[ii * SI + jj * SJ + k], w * scl);
                }
            }
        }
    }
}

// ---------------------------------------------------------------------------
// combine: out = image / (eff + 1e-8) * (bp + bpT^T)
// ---------------------------------------------------------------------------
__global__ void combine_kernel(const float* __restrict__ image,
                               const float* __restrict__ eff,
                               float* __restrict__ out) {
    int tid = blockIdx.x * blockDim.x + threadIdx.x;
    if (tid >= NG3) return;
    int a = tid >> 14;
    int b = (tid >> 7) & 127;
    int c = tid & 127;
    // image voxel (a,b,c) lives at bpT[a][c][b]
    float bpsum = g_bp[tid] + __ldg(&g_bpT[(a << 14) + (c << 7) + b]);
    out[tid] = image[tid] / (eff[tid] + 1e-8f) * bpsum;
}

// ---------------------------------------------------------------------------
extern "C" void kernel_launch(void* const* d_in, const int* in_sizes, int n_in,
                              void* d_out, int out_size) {
    const float* image = (const float*)d_in[0];
    const float* eff   = (const float*)d_in[1];
    const float* xl    = (const float*)d_in[2];
    const float* yl    = (const float*)d_in[3];
    const float* zl    = (const float*)d_in[4];
    float*       out   = (float*)d_out;

    const int n = in_sizes[2] / 6;   // 65536

    void* imgT_p = nullptr;
    void* bp_p   = nullptr;
    void* bpT_p  = nullptr;
    cudaGetSymbolAddress(&imgT_p, g_imgT);
    cudaGetSymbolAddress(&bp_p,   g_bp);
    cudaGetSymbolAddress(&bpT_p,  g_bpT);

    prep_kernel<<<NG3 / 256, 256>>>(image);

    const int nb = (n + 7) / 8;   // 8 warps (LORs) per 256-thread block

    // z: ray along image axis 2; i (comp0) stride 16384, j (comp1) stride 128
    lor_kernel<16384, 128><<<nb, 256>>>(zl, image, (float*)bp_p, n);
    // y: ray along image axis 2; i (comp0) -> image axis1 (128), j -> axis0 (16384)
    lor_kernel<128, 16384><<<nb, 256>>>(yl, image, (float*)bp_p, n);
    // x: ray along image axis 1; uses transposed image + transposed accumulator
    lor_kernel<128, 16384><<<nb, 256>>>(xl, (const float*)imgT_p, (float*)bpT_p, n);

    combine_kernel<<<NG3 / 256, 256>>>(image, eff, out);
}

// round 2
// speedup vs baseline: 1.0256x; 1.0256x over previous
#include <cuda_runtime.h>
#include <cuda_bf16.h>
#include <math.h>

// ---------------------------------------------------------------------------
// PET MLEM step: TOR forward projection + listmode backprojection, 3 LOR sets.
// GRID = 128^3, CENTER = 0, SIZE = 214, N_LORS = 65536 per direction.
//
// R2: forward-gather image stored as bf16 (native + transposed copies) to
// halve the LTS read-sector traffic; atomics remain fp32.
// ---------------------------------------------------------------------------

#define NG   128
#define NG2  (128 * 128)
#define NG3  (128 * 128 * 128)

__device__ __nv_bfloat16 g_imgB [NG3];  // bf16 copy of image, native layout
__device__ __nv_bfloat16 g_imgBT[NG3];  // bf16, imgBT[a][b][c] = image[a][c][b]
__device__ float g_bp [NG3];            // backprojection accumulator (z,y dirs)
__device__ float g_bpT[NG3];            // transposed accumulator (x dir)

__constant__ float C_VOX    = 1.671875f;          // 214/128, exact in fp32
__constant__ float C_XMIN   = -107.0f;
// 1/(2 sigma^2) = pi/(2 vox^2)
__constant__ float C_INV2S2 = 0.561975285171464f;

// ---------------------------------------------------------------------------
// prep: build bf16 image copies (native + transposed)
// ---------------------------------------------------------------------------
__global__ void prep_kernel(const float* __restrict__ image) {
    int tid = blockIdx.x * blockDim.x + threadIdx.x;
    if (tid >= NG3) return;
    int a = tid >> 14;
    int b = (tid >> 7) & 127;
    int c = tid & 127;
    float v = image[tid];
    __nv_bfloat16 h = __float2bfloat16(v);
    g_imgB[tid] = h;
    g_imgBT[(a << 14) + (c << 7) + b] = h;
}

// ---------------------------------------------------------------------------
// LOR kernel: one warp per LOR. Lane L handles planes {L, L+32, L+64, L+96}.
//   voxel (i, j, plane k) address = i*SI + j*SJ + k
//   z-dir: SI=16384, SJ=128   (img = g_imgB,  bp = g_bp)
//   y-dir: SI=128,   SJ=16384 (img = g_imgB,  bp = g_bp)
//   x-dir: SI=128,   SJ=16384 (img = g_imgBT, bp = g_bpT)
// ---------------------------------------------------------------------------
template <int SI, int SJ>
__global__ __launch_bounds__(256)
void lor_kernel(const float* __restrict__ lors,   // [6, n] row-major
                const __nv_bfloat16* __restrict__ img,
                float* __restrict__ bp,
                int n) {
    const int warp = blockIdx.x * 8 + (threadIdx.x >> 5);
    if (warp >= n) return;
    const int lane = threadIdx.x & 31;

    const float p1x = lors[0 * n + warp];
    const float p1y = lors[1 * n + warp];
    const float p1z = lors[2 * n + warp];
    const float p2x = lors[3 * n + warp];
    const float p2y = lors[4 * n + warp];
    const float p2z = lors[5 * n + warp];

    const float dx  = p2x - p1x;
    const float dy  = p2y - p1y;
    const float dzr = p2z - p1z;
    const float L   = sqrtf(dx * dx + dy * dy + dzr * dzr);
    const float dz  = (fabsf(dzr) < 1e-6f) ? 1e-6f : dzr;
    const float dl  = C_VOX * L / fabsf(dz);

    float ex[4][3];
    float ey[4][3];
    int   ib[4];
    int   jb[4];

    float acc = 0.0f;

#pragma unroll
    for (int q = 0; q < 4; q++) {
        const int   k  = lane + 32 * q;
        const float zc = C_XMIN + ((float)k + 0.5f) * C_VOX;     // exact
        const float t  = (zc - p1z) / dz;                        // IEEE div
        const bool  tok = (t >= 0.0f) && (t <= 1.0f);
        // unfused mul+add to match the reference's separate ops
        const float xs = __fadd_rn(p1x, __fmul_rn(t, dx));
        const float ys = __fadd_rn(p1y, __fmul_rn(t, dy));
        const float fi = __fadd_rn(__fdiv_rn(__fsub_rn(xs, C_XMIN), C_VOX), -0.5f);
        const float fj = __fadd_rn(__fdiv_rn(__fsub_rn(ys, C_XMIN), C_VOX), -0.5f);
        const int i0 = __float2int_rn(fi);   // round half-to-even, like jnp.round
        const int j0 = __float2int_rn(fj);
        ib[q] = i0;
        jb[q] = j0;
        const float axc = (float)i0 - fi;    // offset in voxel units
        const float ayc = (float)j0 - fj;

#pragma unroll
        for (int o = 0; o < 3; o++) {
            const float du = (axc + (float)(o - 1)) * C_VOX;
            const float eu = __expf(-du * du * C_INV2S2);
            const int   ii = i0 + o - 1;
            ex[q][o] = (tok && ii >= 0 && ii < NG) ? eu : 0.0f;

            const float dv = (ayc + (float)(o - 1)) * C_VOX;
            const float ev = __expf(-dv * dv * C_INV2S2);
            const int   jj = j0 + o - 1;
            ey[q][o] = (jj >= 0 && jj < NG) ? ev : 0.0f;
        }

        // forward gather (bf16, coalesced along k across the warp)
        if (tok) {
#pragma unroll
            for (int oi = 0; oi < 3; oi++) {
                const int ii = min(max(i0 + oi - 1, 0), NG - 1);
                float inner = 0.0f;
#pragma unroll
                for (int oj = 0; oj < 3; oj++) {
                    const int jj = min(max(j0 + oj - 1, 0), NG - 1);
                    const float v = __bfloat162float(__ldg(&img[ii * SI + jj * SJ + k]));
                    inner = fmaf(ey[q][oj], v, inner);
                }
                acc = fmaf(ex[q][oi], inner, acc);
            }
        }
    }

    // warp-reduce line integral
#pragma unroll
    for (int s = 16; s > 0; s >>= 1)
        acc += __shfl_xor_sync(0xffffffffu, acc, s);

    const float proj = acc * dl;
    const float scl  = dl / (proj + 1e-8f);

    // backprojection scatter (fp32 atomics, coalesced along k across the warp)
#pragma unroll
    for (int q = 0; q < 4; q++) {
        const int k = lane + 32 * q;
#pragma unroll
        for (int oi = 0; oi < 3; oi++) {
            const float exi = ex[q][oi];
            const int   ii  = min(max(ib[q] + oi - 1, 0), NG - 1);
#pragma unroll
            for (int oj = 0; oj < 3; oj++) {
                const float w = exi * ey[q][oj];
                if (w != 0.0f) {
                    const int jj = min(max(jb[q] + oj - 1, 0), NG - 1);
                    atomicAdd(&bp[ii * SI + jj * SJ + k], w * scl);
                }
            }
        }
    }
}

// ---------------------------------------------------------------------------
// combine: out = image / (eff + 1e-8) * (bp + bpT^T)
// ---------------------------------------------------------------------------
__global__ void combine_kernel(const float* __restrict__ image,
                               const float* __restrict__ eff,
                               float* __restrict__ out) {
    int tid = blockIdx.x * blockDim.x + threadIdx.x;
    if (tid >= NG3) return;
    int a = tid >> 14;
    int b = (tid >> 7) & 127;
    int c = tid & 127;
    // image voxel (a,b,c) lives at bpT[a][c][b]
    float bpsum = g_bp[tid] + __ldg(&g_bpT[(a << 14) + (c << 7) + b]);
    out[tid] = image[tid] / (eff[tid] + 1e-8f) * bpsum;
}

// ---------------------------------------------------------------------------
extern "C" void kernel_launch(void* const* d_in, const int* in_sizes, int n_in,
                              void* d_out, int out_size) {
    const float* image = (const float*)d_in[0];
    const float* eff   = (const float*)d_in[1];
    const float* xl    = (const float*)d_in[2];
    const float* yl    = (const float*)d_in[3];
    const float* zl    = (const float*)d_in[4];
    float*       out   = (float*)d_out;

    const int n = in_sizes[2] / 6;   // 65536

    void* imgB_p  = nullptr;
    void* imgBT_p = nullptr;
    void* bp_p    = nullptr;
    void* bpT_p   = nullptr;
    cudaGetSymbolAddress(&imgB_p,  g_imgB);
    cudaGetSymbolAddress(&imgBT_p, g_imgBT);
    cudaGetSymbolAddress(&bp_p,    g_bp);
    cudaGetSymbolAddress(&bpT_p,   g_bpT);

    cudaMemsetAsync(bp_p,  0, NG3 * sizeof(float));
    cudaMemsetAsync(bpT_p, 0, NG3 * sizeof(float));

    prep_kernel<<<NG3 / 256, 256>>>(image);

    const int nb = (n + 7) / 8;   // 8 warps (LORs) per 256-thread block

    // z: ray along image axis 2; i stride 16384, j stride 128
    lor_kernel<16384, 128><<<nb, 256>>>(zl, (const __nv_bfloat16*)imgB_p,
                                        (float*)bp_p, n);
    // y: ray along image axis 2; i -> image axis1 (128), j -> axis0 (16384)
    lor_kernel<128, 16384><<<nb, 256>>>(yl, (const __nv_bfloat16*)imgB_p,
                                        (float*)bp_p, n);
    // x: ray along image axis 1; transposed image + transposed accumulator
    lor_kernel<128, 16384><<<nb, 256>>>(xl, (const __nv_bfloat16*)imgBT_p,
                                        (float*)bpT_p, n);

    combine_kernel<<<NG3 / 256, 256>>>(image, eff, out);
}